// round 15
// baseline (speedup 1.0000x reference)
#include <cuda_runtime.h>
#include <cuda_bf16.h>

// Batched Kalman update: B=262144, DX=8, DZ=4.  ONE thread per batch.
//
// Design: warp-local everything (zero __syncthreads; only __syncwarp).
// Warp w of a 64-thread block owns batches 32w..32w+31: it stages its own
// P/x records into smem, computes, and drains its own contiguous span.
// SREG=19 (odd): thread-t record base 19t -> any 8-lane phase hits
// 3t mod 8 = all-distinct bank-quads: every LDS/STS.128 conflict-free.
// H kept in 32 registers (NT=64 @ 11 CTAs allows 93 regs); R upper in 10.
// No pair communication: no shuffles, single Cholesky per batch.
//
// W-form math (== Joseph form for the optimal gain):
//   PHT = P H^T, S = H PHT + R = L L^T;  W = PHT L^-T,  u = L^-1 y
//   x_new = x + W u,  P_new = P - W W^T

#define NT   64
#define BPB  64
#define SREG 19

__global__ void __launch_bounds__(NT, 11) kalman_kernel(
    const float4* __restrict__ x4,
    const float4* __restrict__ z4,
    const float4* __restrict__ P4,
    const float*  __restrict__ Hg,
    const float*  __restrict__ Rg,
    float4*       __restrict__ out4,
    int nb)
{
    __shared__ float4 Buf4[BPB * SREG];   // 19456 B; warp w owns [32w*19, +608)

    const int t    = threadIdx.x;
    const int w    = t >> 5;
    const int lane = t & 31;
    const int b0   = blockIdx.x * BPB;
    const int nbb  = min(BPB, nb - b0);
    const int mw0  = w * 32;
    const int nw   = min(32, nbb - mw0);

    // ---- H rows -> 32 registers (broadcast LDG); R upper -> 10 regs ----
    float hr[4][8];
    #pragma unroll
    for (int c = 0; c < 4; c++) {
        float4 a = __ldg((const float4*)(Hg + 8 * c));
        float4 b = __ldg((const float4*)(Hg + 8 * c + 4));
        hr[c][0] = a.x; hr[c][1] = a.y; hr[c][2] = a.z; hr[c][3] = a.w;
        hr[c][4] = b.x; hr[c][5] = b.y; hr[c][6] = b.z; hr[c][7] = b.w;
    }
    float r00, r01, r02, r03, r11, r12, r13, r22, r23, r33;
    {
        float4 q0 = __ldg((const float4*)(Rg));
        float4 q1 = __ldg((const float4*)(Rg + 4));
        float4 q2 = __ldg((const float4*)(Rg + 8));
        float4 q3 = __ldg((const float4*)(Rg + 12));
        r00 = q0.x; r01 = q0.y; r02 = q0.z; r03 = q0.w;
        r11 = q1.y; r12 = q1.z; r13 = q1.w;
        r22 = q2.z; r23 = q2.w; r33 = q3.w;
    }

    if (nw > 0) {
        // ---- Warp-local stage P: coalesced LDG.128, conflict-free STS.128 ----
        {
            const int hw = lane >> 4;      // 0/1
            const int fq = lane & 15;      // quad-in-record
            #pragma unroll
            for (int k = 0; k < 16; k++) {
                int ml = hw + 2 * k;       // 0..31
                if (ml < nw)
                    Buf4[(mw0 + ml) * SREG + 2 + fq] =
                        P4[(size_t)b0 * 16 + 16 * (mw0 + ml) + fq];
            }
        }
        // ---- Warp-local stage x (2 quads/record) ----
        #pragma unroll
        for (int k = 0; k < 2; k++) {
            int idx = lane + 32 * k;       // 0..63
            int ml = idx >> 1, f = idx & 1;
            if (ml < nw)
                Buf4[(mw0 + ml) * SREG + f] = x4[(size_t)(b0 + mw0) * 2 + idx];
        }

        __syncwarp();

        if (lane < nw) {
            const int rb = (mw0 + lane) * SREG;

            // ---- y = z - H x ----
            float y0, y1, y2, y3;
            {
                float4 zq  = z4[b0 + mw0 + lane];
                float4 xq0 = Buf4[rb];
                float4 xq1 = Buf4[rb + 1];
                float x0 = xq0.x, x1 = xq0.y, x2 = xq0.z, x3 = xq0.w;
                float x4v = xq1.x, x5 = xq1.y, x6 = xq1.z, x7 = xq1.w;
                y0 = zq.x - (hr[0][0]*x0 + hr[0][1]*x1 + hr[0][2]*x2 + hr[0][3]*x3
                           + hr[0][4]*x4v + hr[0][5]*x5 + hr[0][6]*x6 + hr[0][7]*x7);
                y1 = zq.y - (hr[1][0]*x0 + hr[1][1]*x1 + hr[1][2]*x2 + hr[1][3]*x3
                           + hr[1][4]*x4v + hr[1][5]*x5 + hr[1][6]*x6 + hr[1][7]*x7);
                y2 = zq.z - (hr[2][0]*x0 + hr[2][1]*x1 + hr[2][2]*x2 + hr[2][3]*x3
                           + hr[2][4]*x4v + hr[2][5]*x5 + hr[2][6]*x6 + hr[2][7]*x7);
                y3 = zq.w - (hr[3][0]*x0 + hr[3][1]*x1 + hr[3][2]*x2 + hr[3][3]*x3
                           + hr[3][4]*x4v + hr[3][5]*x5 + hr[3][6]*x6 + hr[3][7]*x7);
            }

            // ---- W = P H^T  [8][4] (row-wise reads, conflict-free) ----
            float W[8][4];
            #pragma unroll
            for (int i = 0; i < 8; i++) {
                float4 qa = Buf4[rb + 2 + 2 * i];
                float4 qb = Buf4[rb + 3 + 2 * i];
                #pragma unroll
                for (int c = 0; c < 4; c++) {
                    W[i][c] = qa.x*hr[c][0] + qa.y*hr[c][1] + qa.z*hr[c][2] + qa.w*hr[c][3]
                            + qb.x*hr[c][4] + qb.y*hr[c][5] + qb.z*hr[c][6] + qb.w*hr[c][7];
                }
            }

            // ---- S = H W + R (upper triangle) ----
            float S00 = r00, S01 = r01, S02 = r02, S03 = r03;
            float S11 = r11, S12 = r12, S13 = r13;
            float S22 = r22, S23 = r23, S33 = r33;
            #pragma unroll
            for (int i = 0; i < 8; i++) {
                float q0 = W[i][0], q1 = W[i][1], q2 = W[i][2], q3 = W[i][3];
                float h0 = hr[0][i], h1 = hr[1][i], h2 = hr[2][i], h3 = hr[3][i];
                S00 += h0 * q0; S01 += h0 * q1; S02 += h0 * q2; S03 += h0 * q3;
                S11 += h1 * q1; S12 += h1 * q2; S13 += h1 * q3;
                S22 += h2 * q2; S23 += h2 * q3;
                S33 += h3 * q3;
            }

            // ---- Cholesky ----
            float i0  = rsqrtf(S00);
            float l10 = S01 * i0, l20 = S02 * i0, l30 = S03 * i0;
            float i1  = rsqrtf(S11 - l10 * l10);
            float l21 = (S12 - l20 * l10) * i1;
            float l31 = (S13 - l30 * l10) * i1;
            float i2  = rsqrtf(S22 - l20 * l20 - l21 * l21);
            float l32 = (S23 - l30 * l20 - l31 * l21) * i2;
            float i3  = rsqrtf(S33 - l30 * l30 - l31 * l31 - l32 * l32);

            // ---- W <- W L^-T (8 rows, independent) ----
            #pragma unroll
            for (int i = 0; i < 8; i++) {
                float w0 = W[i][0] * i0;
                float w1 = (W[i][1] - l10 * w0) * i1;
                float w2 = (W[i][2] - l20 * w0 - l21 * w1) * i2;
                float w3 = (W[i][3] - l30 * w0 - l31 * w1 - l32 * w2) * i3;
                W[i][0] = w0; W[i][1] = w1; W[i][2] = w2; W[i][3] = w3;
            }

            // ---- u = L^-1 y ----
            float u0 = y0 * i0;
            float u1 = (y1 - l10 * u0) * i1;
            float u2 = (y2 - l20 * u0 - l21 * u1) * i2;
            float u3 = (y3 - l30 * u0 - l31 * u1 - l32 * u2) * i3;

            // ---- x_new = x + W u (re-read x, overwrite with result) ----
            {
                float4 xq0 = Buf4[rb];
                float4 xq1 = Buf4[rb + 1];
                Buf4[rb] = make_float4(
                    xq0.x + W[0][0]*u0 + W[0][1]*u1 + W[0][2]*u2 + W[0][3]*u3,
                    xq0.y + W[1][0]*u0 + W[1][1]*u1 + W[1][2]*u2 + W[1][3]*u3,
                    xq0.z + W[2][0]*u0 + W[2][1]*u1 + W[2][2]*u2 + W[2][3]*u3,
                    xq0.w + W[3][0]*u0 + W[3][1]*u1 + W[3][2]*u2 + W[3][3]*u3);
                Buf4[rb + 1] = make_float4(
                    xq1.x + W[4][0]*u0 + W[4][1]*u1 + W[4][2]*u2 + W[4][3]*u3,
                    xq1.y + W[5][0]*u0 + W[5][1]*u1 + W[5][2]*u2 + W[5][3]*u3,
                    xq1.z + W[6][0]*u0 + W[6][1]*u1 + W[6][2]*u2 + W[6][3]*u3,
                    xq1.w + W[7][0]*u0 + W[7][1]*u1 + W[7][2]*u2 + W[7][3]*u3);
            }

            // ---- P_new = P - W W^T (row at a time, in place) ----
            #pragma unroll
            for (int i = 0; i < 8; i++) {
                float4 qa = Buf4[rb + 2 + 2 * i];
                float4 qb = Buf4[rb + 3 + 2 * i];
                float po[8] = { qa.x, qa.y, qa.z, qa.w, qb.x, qb.y, qb.z, qb.w };
                float w0 = W[i][0], w1 = W[i][1], w2 = W[i][2], w3 = W[i][3];
                #pragma unroll
                for (int j = 0; j < 8; j++)
                    po[j] -= w0 * W[j][0] + w1 * W[j][1] + w2 * W[j][2] + w3 * W[j][3];
                Buf4[rb + 2 + 2 * i] = make_float4(po[0], po[1], po[2], po[3]);
                Buf4[rb + 3 + 2 * i] = make_float4(po[4], po[5], po[6], po[7]);
            }
        }

        __syncwarp();

        // ---- Warp-local drain: quads 0..17 of each record -> gmem ----
        {
            const int total = nw * 18;
            #pragma unroll
            for (int k = 0; k < 18; k++) {
                int idx = lane + 32 * k;           // 0..575
                if (idx < total) {
                    int mm = idx / 18;
                    int j  = idx - mm * 18;
                    out4[((size_t)(b0 + mw0)) * 18 + idx] =
                        Buf4[(mw0 + mm) * SREG + j];
                }
            }
        }
    }
}

extern "C" void kernel_launch(void* const* d_in, const int* in_sizes, int n_in,
                              void* d_out, int out_size) {
    const float4* x4 = (const float4*)d_in[0];
    const float4* z4 = (const float4*)d_in[1];
    const float4* P4 = (const float4*)d_in[2];
    const float*  Hg = (const float*)d_in[3];
    const float*  Rg = (const float*)d_in[4];
    float4* out4 = (float4*)d_out;

    int nb = in_sizes[0] / 8;            // B
    int grid = (nb + BPB - 1) / BPB;
    kalman_kernel<<<grid, NT>>>(x4, z4, P4, Hg, Rg, out4, nb);
}

// round 16
// speedup vs baseline: 1.3417x; 1.3417x over previous
#include <cuda_runtime.h>
#include <cuda.h>
#include <cuda_bf16.h>

// Batched Kalman update: B=262144, DX=8, DZ=4.  TWO threads per batch.
// Pair = lanes (2m, 2m+1); thread h owns rows 4h..4h+3.
//
// P is loaded by TMA with a SW128-swizzled 3D map [128B][2][B]: record ml
// occupies smem rows 2ml (P-rows 0..3) and 2ml+1 (P-rows 4..7); 16B chunk c
// of row r lands at quad (8r + (c ^ (r&7))). Thread h reads rows r=2ml+h
// (parity h) and chunks c=2ii (+1), giving 8-lane phase bank-quads
// {even set for h0} U {odd set for h1}: conflict-free for every access.
// P_new is written back in place and stored by a matching SW128 map
// (record stride 288 = output) which de-swizzles; x_new goes via a small
// unswizzled 2D map. No LDG/STS staging of P at all.
//
// W-form math (== Joseph form for the optimal gain):
//   PHT = P H^T, S = H PHT + R = L L^T;  W = PHT L^-T,  u = L^-1 y
//   x_new = x + W u,  P_new = P - W W^T
//
// Tensor maps are encoded host-side each call via
// cudaGetDriverEntryPoint("cuTensorMapEncodeTiled") (no -lcuda needed) and
// passed __grid_constant__. If anything fails, we fall back to the proven
// R12 kernel (29.4us).

#define NT   128
#define BPB  64

// ===========================================================================
// TMA kernel
// ===========================================================================
__global__ void __launch_bounds__(NT, 8) kalman_tma(
    const float4* __restrict__ x4,
    const float4* __restrict__ z4,
    const float*  __restrict__ Hg,
    const float*  __restrict__ Rg,
    int nb,
    const __grid_constant__ CUtensorMap mL,   // P load  [128B][2][B] SW128
    const __grid_constant__ CUtensorMap mP,   // P store [128B][2][B] SW128, stride 288
    const __grid_constant__ CUtensorMap mX)   // x store [32B][B]
{
    __shared__ alignas(1024) float4 Psw4[BPB * 16];  // 16 KB swizzled P image
    __shared__ float4 xs4[BPB * 2];                  // 2 KB x_new staging
    __shared__ float4 HT4[8];                        // HT4[k] = H[0..3][k]
    __shared__ float  Rs[16];
    __shared__ unsigned long long mbar;

    const int t   = threadIdx.x;
    const int b0  = blockIdx.x * BPB;
    const int nbb = min(BPB, nb - b0);

    if (t < 8)  HT4[t] = make_float4(Hg[t], Hg[8 + t], Hg[16 + t], Hg[24 + t]);
    if (t >= 32 && t < 48) Rs[t - 32] = Rg[t - 32];

    const unsigned mb = (unsigned)__cvta_generic_to_shared(&mbar);
    if (t == 0)
        asm volatile("mbarrier.init.shared.b64 [%0], 1;" :: "r"(mb) : "memory");
    __syncthreads();

    if (t == 0) {
        asm volatile("mbarrier.arrive.expect_tx.shared.b64 _, [%0], %1;"
                     :: "r"(mb), "r"(16384u) : "memory");
        unsigned sp = (unsigned)__cvta_generic_to_shared(&Psw4[0]);
        asm volatile(
            "cp.async.bulk.tensor.3d.shared::cta.global.tile.mbarrier::complete_tx::bytes "
            "[%0], [%1, {%2, %3, %4}], [%5];"
            :: "r"(sp), "l"((unsigned long long)&mL),
               "r"(0), "r"(0), "r"(b0), "r"(mb) : "memory");
    }

    // Direct x/z loads (coalesced; land on owning threads)
    float4 xq = make_float4(0.f, 0.f, 0.f, 0.f);
    float4 zq = make_float4(0.f, 0.f, 0.f, 0.f);
    if (t < 2 * nbb) {
        xq = x4[(size_t)b0 * 2 + t];
        zq = z4[b0 + (t >> 1)];
    }

    // Wait for TMA load (phase 0: fresh mbarrier each launch)
    asm volatile(
        "{\n\t.reg .pred P1;\n\t"
        "WL%=:\n\t"
        "mbarrier.try_wait.parity.acquire.cta.shared::cta.b64 P1, [%0], 0, 0x989680;\n\t"
        "@P1 bra WD%=;\n\t"
        "bra WL%=;\n\t"
        "WD%=:\n\t}"
        :: "r"(mb) : "memory");

    if (t < 2 * nbb) {
        const int ml = t >> 1;
        const int h  = t & 1;
        const int A  = 16 * ml + 8 * h;        // base quad of smem row 2ml+h
        const int k8 = (2 * ml + h) & 7;       // swizzle key of that row
        const int hb = 4 * h;
        const unsigned FM = 0xffffffffu;

        // ---- y = z - H x (pair-partial; own elems are cols 4h..4h+3) ----
        float xo0 = xq.x, xo1 = xq.y, xo2 = xq.z, xo3 = xq.w;
        float s0, s1, s2, s3;
        {
            float4 ha = HT4[hb + 0], hbq = HT4[hb + 1];
            float4 hc = HT4[hb + 2], hd  = HT4[hb + 3];
            s0 = ha.x * xo0 + hbq.x * xo1 + hc.x * xo2 + hd.x * xo3;
            s1 = ha.y * xo0 + hbq.y * xo1 + hc.y * xo2 + hd.y * xo3;
            s2 = ha.z * xo0 + hbq.z * xo1 + hc.z * xo2 + hd.z * xo3;
            s3 = ha.w * xo0 + hbq.w * xo1 + hc.w * xo2 + hd.w * xo3;
        }
        float y0 = zq.x - (s0 + __shfl_xor_sync(FM, s0, 1));
        float y1 = zq.y - (s1 + __shfl_xor_sync(FM, s1, 1));
        float y2 = zq.z - (s2 + __shfl_xor_sync(FM, s2, 1));
        float y3 = zq.w - (s3 + __shfl_xor_sync(FM, s3, 1));

        // ---- W = PHT for own rows 4h+ii (swizzled quad reads) ----
        // qa = cols 0..3 (chunk 2ii), qb = cols 4..7 (chunk 2ii+1); h-independent H use.
        float W[4][4];
        #pragma unroll
        for (int ii = 0; ii < 4; ii++) {
            const int ca = (2 * ii) ^ k8;
            float4 qa = Psw4[A + ca];
            float4 qb = Psw4[A + (ca ^ 1)];
            float q0, q1, q2, q3;
            {
                float4 c0 = HT4[0], c1 = HT4[1], c2 = HT4[2], c3 = HT4[3];
                q0 = qa.x * c0.x + qa.y * c1.x + qa.z * c2.x + qa.w * c3.x;
                q1 = qa.x * c0.y + qa.y * c1.y + qa.z * c2.y + qa.w * c3.y;
                q2 = qa.x * c0.z + qa.y * c1.z + qa.z * c2.z + qa.w * c3.z;
                q3 = qa.x * c0.w + qa.y * c1.w + qa.z * c2.w + qa.w * c3.w;
            }
            {
                float4 c4 = HT4[4], c5 = HT4[5], c6 = HT4[6], c7 = HT4[7];
                q0 += qb.x * c4.x + qb.y * c5.x + qb.z * c6.x + qb.w * c7.x;
                q1 += qb.x * c4.y + qb.y * c5.y + qb.z * c6.y + qb.w * c7.y;
                q2 += qb.x * c4.z + qb.y * c5.z + qb.z * c6.z + qb.w * c7.z;
                q3 += qb.x * c4.w + qb.y * c5.w + qb.z * c6.w + qb.w * c7.w;
            }
            W[ii][0] = q0; W[ii][1] = q1; W[ii][2] = q2; W[ii][3] = q3;
        }

        // ---- S partial from own rows, then pair-reduce ----
        float S00 = 0.f, S01 = 0.f, S02 = 0.f, S03 = 0.f;
        float S11 = 0.f, S12 = 0.f, S13 = 0.f;
        float S22 = 0.f, S23 = 0.f, S33 = 0.f;
        #pragma unroll
        for (int i = 0; i < 4; i++) {
            float4 ht = HT4[hb + i];
            float q0 = W[i][0], q1 = W[i][1], q2 = W[i][2], q3 = W[i][3];
            S00 += ht.x * q0; S01 += ht.x * q1; S02 += ht.x * q2; S03 += ht.x * q3;
            S11 += ht.y * q1; S12 += ht.y * q2; S13 += ht.y * q3;
            S22 += ht.z * q2; S23 += ht.z * q3;
            S33 += ht.w * q3;
        }
        S00 += __shfl_xor_sync(FM, S00, 1); S01 += __shfl_xor_sync(FM, S01, 1);
        S02 += __shfl_xor_sync(FM, S02, 1); S03 += __shfl_xor_sync(FM, S03, 1);
        S11 += __shfl_xor_sync(FM, S11, 1); S12 += __shfl_xor_sync(FM, S12, 1);
        S13 += __shfl_xor_sync(FM, S13, 1); S22 += __shfl_xor_sync(FM, S22, 1);
        S23 += __shfl_xor_sync(FM, S23, 1); S33 += __shfl_xor_sync(FM, S33, 1);
        S00 += Rs[0];  S01 += Rs[1];  S02 += Rs[2];  S03 += Rs[3];
        S11 += Rs[5];  S12 += Rs[6];  S13 += Rs[7];
        S22 += Rs[10]; S23 += Rs[11]; S33 += Rs[15];

        // ---- Cholesky ----
        float i0  = rsqrtf(S00);
        float l10 = S01 * i0, l20 = S02 * i0, l30 = S03 * i0;
        float i1  = rsqrtf(S11 - l10 * l10);
        float l21 = (S12 - l20 * l10) * i1;
        float l31 = (S13 - l30 * l10) * i1;
        float i2  = rsqrtf(S22 - l20 * l20 - l21 * l21);
        float l32 = (S23 - l30 * l20 - l31 * l21) * i2;
        float i3  = rsqrtf(S33 - l30 * l30 - l31 * l31 - l32 * l32);

        // ---- W <- W L^-T ----
        #pragma unroll
        for (int i = 0; i < 4; i++) {
            float w0 = W[i][0] * i0;
            float w1 = (W[i][1] - l10 * w0) * i1;
            float w2 = (W[i][2] - l20 * w0 - l21 * w1) * i2;
            float w3 = (W[i][3] - l30 * w0 - l31 * w1 - l32 * w2) * i3;
            W[i][0] = w0; W[i][1] = w1; W[i][2] = w2; W[i][3] = w3;
        }

        // ---- u = L^-1 y ----
        float u0 = y0 * i0;
        float u1 = (y1 - l10 * u0) * i1;
        float u2 = (y2 - l20 * u0 - l21 * u1) * i2;
        float u3 = (y3 - l30 * u0 - l31 * u1 - l32 * u2) * i3;

        // ---- x_new own quad (elems 4h..4h+3 pair with own W rows) ----
        xs4[2 * ml + h] = make_float4(
            xo0 + W[0][0]*u0 + W[0][1]*u1 + W[0][2]*u2 + W[0][3]*u3,
            xo1 + W[1][0]*u0 + W[1][1]*u1 + W[1][2]*u2 + W[1][3]*u3,
            xo2 + W[2][0]*u0 + W[2][1]*u1 + W[2][2]*u2 + W[2][3]*u3,
            xo3 + W[3][0]*u0 + W[3][1]*u1 + W[3][2]*u2 + W[3][3]*u3);

        // ---- Partner W via 16 xor-shuffles (pW[s] = W row 4(1-h)+s) ----
        float pW[4][4];
        #pragma unroll
        for (int s = 0; s < 4; s++)
            #pragma unroll
            for (int c = 0; c < 4; c++)
                pW[s][c] = __shfl_xor_sync(FM, W[s][c], 1);

        // ---- P_new = P - W W^T, two 2-row halves (regs <= 64) ----
        // cols 0..3 pair with global rows 0..3 = (h? pW : W)
        // cols 4..7 pair with global rows 4..7 = (h? W : pW)
        #pragma unroll
        for (int half = 0; half < 2; half++) {
            float po[2][8];
            int caA[2];
            #pragma unroll
            for (int ii = 0; ii < 2; ii++) {
                const int i = 2 * half + ii;
                caA[ii] = (2 * i) ^ k8;
                float4 qa = Psw4[A + caA[ii]];
                float4 qb = Psw4[A + (caA[ii] ^ 1)];
                po[ii][0] = qa.x; po[ii][1] = qa.y; po[ii][2] = qa.z; po[ii][3] = qa.w;
                po[ii][4] = qb.x; po[ii][5] = qb.y; po[ii][6] = qb.z; po[ii][7] = qb.w;
            }
            #pragma unroll
            for (int g = 0; g < 8; g++) {
                const int s = g & 3;
                float wg0, wg1, wg2, wg3;
                if (g < 4) {
                    wg0 = h ? pW[s][0] : W[s][0];
                    wg1 = h ? pW[s][1] : W[s][1];
                    wg2 = h ? pW[s][2] : W[s][2];
                    wg3 = h ? pW[s][3] : W[s][3];
                } else {
                    wg0 = h ? W[s][0] : pW[s][0];
                    wg1 = h ? W[s][1] : pW[s][1];
                    wg2 = h ? W[s][2] : pW[s][2];
                    wg3 = h ? W[s][3] : pW[s][3];
                }
                #pragma unroll
                for (int ii = 0; ii < 2; ii++) {
                    const int i = 2 * half + ii;
                    po[ii][g] -= W[i][0] * wg0 + W[i][1] * wg1
                               + W[i][2] * wg2 + W[i][3] * wg3;
                }
            }
            #pragma unroll
            for (int ii = 0; ii < 2; ii++) {
                Psw4[A + caA[ii]]       = make_float4(po[ii][0], po[ii][1], po[ii][2], po[ii][3]);
                Psw4[A + (caA[ii] ^ 1)] = make_float4(po[ii][4], po[ii][5], po[ii][6], po[ii][7]);
            }
        }
    }

    __syncthreads();

    // ---- Drain: 2 TMA stores (P de-swizzled into records, x-part) ----
    if (t == 0) {
        asm volatile("fence.proxy.async.shared::cta;" ::: "memory");
        unsigned sp = (unsigned)__cvta_generic_to_shared(&Psw4[0]);
        unsigned sx = (unsigned)__cvta_generic_to_shared(&xs4[0]);
        asm volatile(
            "cp.async.bulk.tensor.3d.global.shared::cta.tile.bulk_group "
            "[%0, {%1, %2, %3}], [%4];"
            :: "l"((unsigned long long)&mP), "r"(0), "r"(0), "r"(b0), "r"(sp) : "memory");
        asm volatile(
            "cp.async.bulk.tensor.2d.global.shared::cta.tile.bulk_group "
            "[%0, {%1, %2}], [%3];"
            :: "l"((unsigned long long)&mX), "r"(0), "r"(b0), "r"(sx) : "memory");
        asm volatile("cp.async.bulk.commit_group;" ::: "memory");
        asm volatile("cp.async.bulk.wait_group.read 0;" ::: "memory");
    }
}

// ===========================================================================
// Fallback: proven R12 kernel (29.4us) — used if tensormap encode unavailable
// ===========================================================================
#define SREG 18

__global__ void __launch_bounds__(NT, 8) kalman_fb(
    const float4* __restrict__ x4,
    const float4* __restrict__ z4,
    const float4* __restrict__ P4,
    const float*  __restrict__ Hg,
    const float*  __restrict__ Rg,
    float4*       __restrict__ out4,
    int nb)
{
    __shared__ float4 Buf4[BPB * SREG];
    __shared__ float4 HT4[8];
    __shared__ float  Rs[16];

    const int t   = threadIdx.x;
    const int b0  = blockIdx.x * BPB;
    const int nbb = min(BPB, nb - b0);

    if (t < 8)  HT4[t] = make_float4(Hg[t], Hg[8 + t], Hg[16 + t], Hg[24 + t]);
    if (t >= 32 && t < 48) Rs[t - 32] = Rg[t - 32];

    {
        const int hw = t >> 4;
        const int fq = t & 15;
        #pragma unroll
        for (int k = 0; k < 8; k++) {
            int m = hw + 8 * k;
            if (m < nbb)
                Buf4[m * SREG + 2 + fq] = P4[(size_t)b0 * 16 + 16 * m + fq];
        }
    }
    float4 xq = make_float4(0.f, 0.f, 0.f, 0.f);
    float4 zq = make_float4(0.f, 0.f, 0.f, 0.f);
    if (t < 2 * nbb) {
        xq = x4[(size_t)b0 * 2 + t];
        zq = z4[b0 + (t >> 1)];
    }
    __syncthreads();

    if (t < 2 * nbb) {
        const int m  = t >> 1;
        const int h  = t & 1;
        const int rb = m * SREG;
        const int hb1 = 4 * h;
        const int hb2 = 4 - 4 * h;
        const unsigned FM = 0xffffffffu;

        float xo0 = xq.x, xo1 = xq.y, xo2 = xq.z, xo3 = xq.w;
        float s0, s1, s2, s3;
        {
            float4 ha = HT4[hb1 + 0], hb = HT4[hb1 + 1];
            float4 hc = HT4[hb1 + 2], hd = HT4[hb1 + 3];
            s0 = ha.x * xo0 + hb.x * xo1 + hc.x * xo2 + hd.x * xo3;
            s1 = ha.y * xo0 + hb.y * xo1 + hc.y * xo2 + hd.y * xo3;
            s2 = ha.z * xo0 + hb.z * xo1 + hc.z * xo2 + hd.z * xo3;
            s3 = ha.w * xo0 + hb.w * xo1 + hc.w * xo2 + hd.w * xo3;
        }
        float y0 = zq.x - (s0 + __shfl_xor_sync(FM, s0, 1));
        float y1 = zq.y - (s1 + __shfl_xor_sync(FM, s1, 1));
        float y2 = zq.z - (s2 + __shfl_xor_sync(FM, s2, 1));
        float y3 = zq.w - (s3 + __shfl_xor_sync(FM, s3, 1));

        float W[4][4];
        #pragma unroll
        for (int i = 0; i < 4; i++) {
            const int A = rb + 2 + 8 * h + 2 * i;
            float4 qa = Buf4[A + h];
            float4 qb = Buf4[A + 1 - h];
            float q0, q1, q2, q3;
            {
                float4 c0 = HT4[hb1 + 0], c1 = HT4[hb1 + 1];
                float4 c2 = HT4[hb1 + 2], c3 = HT4[hb1 + 3];
                q0 = qa.x * c0.x + qa.y * c1.x + qa.z * c2.x + qa.w * c3.x;
                q1 = qa.x * c0.y + qa.y * c1.y + qa.z * c2.y + qa.w * c3.y;
                q2 = qa.x * c0.z + qa.y * c1.z + qa.z * c2.z + qa.w * c3.z;
                q3 = qa.x * c0.w + qa.y * c1.w + qa.z * c2.w + qa.w * c3.w;
            }
            {
                float4 c0 = HT4[hb2 + 0], c1 = HT4[hb2 + 1];
                float4 c2 = HT4[hb2 + 2], c3 = HT4[hb2 + 3];
                q0 += qb.x * c0.x + qb.y * c1.x + qb.z * c2.x + qb.w * c3.x;
                q1 += qb.x * c0.y + qb.y * c1.y + qb.z * c2.y + qb.w * c3.y;
                q2 += qb.x * c0.z + qb.y * c1.z + qb.z * c2.z + qb.w * c3.z;
                q3 += qb.x * c0.w + qb.y * c1.w + qb.z * c2.w + qb.w * c3.w;
            }
            W[i][0] = q0; W[i][1] = q1; W[i][2] = q2; W[i][3] = q3;
        }

        float S00 = 0.f, S01 = 0.f, S02 = 0.f, S03 = 0.f;
        float S11 = 0.f, S12 = 0.f, S13 = 0.f;
        float S22 = 0.f, S23 = 0.f, S33 = 0.f;
        #pragma unroll
        for (int i = 0; i < 4; i++) {
            float4 ht = HT4[hb1 + i];
            float q0 = W[i][0], q1 = W[i][1], q2 = W[i][2], q3 = W[i][3];
            S00 += ht.x * q0; S01 += ht.x * q1; S02 += ht.x * q2; S03 += ht.x * q3;
            S11 += ht.y * q1; S12 += ht.y * q2; S13 += ht.y * q3;
            S22 += ht.z * q2; S23 += ht.z * q3;
            S33 += ht.w * q3;
        }
        S00 += __shfl_xor_sync(FM, S00, 1); S01 += __shfl_xor_sync(FM, S01, 1);
        S02 += __shfl_xor_sync(FM, S02, 1); S03 += __shfl_xor_sync(FM, S03, 1);
        S11 += __shfl_xor_sync(FM, S11, 1); S12 += __shfl_xor_sync(FM, S12, 1);
        S13 += __shfl_xor_sync(FM, S13, 1); S22 += __shfl_xor_sync(FM, S22, 1);
        S23 += __shfl_xor_sync(FM, S23, 1); S33 += __shfl_xor_sync(FM, S33, 1);
        S00 += Rs[0];  S01 += Rs[1];  S02 += Rs[2];  S03 += Rs[3];
        S11 += Rs[5];  S12 += Rs[6];  S13 += Rs[7];
        S22 += Rs[10]; S23 += Rs[11]; S33 += Rs[15];

        float i0  = rsqrtf(S00);
        float l10 = S01 * i0, l20 = S02 * i0, l30 = S03 * i0;
        float i1  = rsqrtf(S11 - l10 * l10);
        float l21 = (S12 - l20 * l10) * i1;
        float l31 = (S13 - l30 * l10) * i1;
        float i2  = rsqrtf(S22 - l20 * l20 - l21 * l21);
        float l32 = (S23 - l30 * l20 - l31 * l21) * i2;
        float i3  = rsqrtf(S33 - l30 * l30 - l31 * l31 - l32 * l32);

        #pragma unroll
        for (int i = 0; i < 4; i++) {
            float w0 = W[i][0] * i0;
            float w1 = (W[i][1] - l10 * w0) * i1;
            float w2 = (W[i][2] - l20 * w0 - l21 * w1) * i2;
            float w3 = (W[i][3] - l30 * w0 - l31 * w1 - l32 * w2) * i3;
            W[i][0] = w0; W[i][1] = w1; W[i][2] = w2; W[i][3] = w3;
        }

        float u0 = y0 * i0;
        float u1 = (y1 - l10 * u0) * i1;
        float u2 = (y2 - l20 * u0 - l21 * u1) * i2;
        float u3 = (y3 - l30 * u0 - l31 * u1 - l32 * u2) * i3;

        Buf4[rb + h] = make_float4(
            xo0 + W[0][0]*u0 + W[0][1]*u1 + W[0][2]*u2 + W[0][3]*u3,
            xo1 + W[1][0]*u0 + W[1][1]*u1 + W[1][2]*u2 + W[1][3]*u3,
            xo2 + W[2][0]*u0 + W[2][1]*u1 + W[2][2]*u2 + W[2][3]*u3,
            xo3 + W[3][0]*u0 + W[3][1]*u1 + W[3][2]*u2 + W[3][3]*u3);

        float pW[4][4];
        #pragma unroll
        for (int s = 0; s < 4; s++)
            #pragma unroll
            for (int c = 0; c < 4; c++)
                pW[s][c] = __shfl_xor_sync(FM, W[s][c], 1);

        #pragma unroll
        for (int half = 0; half < 2; half++) {
            float po[2][8];
            #pragma unroll
            for (int ii = 0; ii < 2; ii++) {
                const int i = 2 * half + ii;
                const int A = rb + 2 + 8 * h + 2 * i;
                float4 qa = Buf4[A + h];
                float4 qb = Buf4[A + 1 - h];
                po[ii][0] = qa.x; po[ii][1] = qa.y; po[ii][2] = qa.z; po[ii][3] = qa.w;
                po[ii][4] = qb.x; po[ii][5] = qb.y; po[ii][6] = qb.z; po[ii][7] = qb.w;
            }
            #pragma unroll
            for (int ii = 0; ii < 2; ii++) {
                const int i = 2 * half + ii;
                float w0 = W[i][0], w1 = W[i][1], w2 = W[i][2], w3 = W[i][3];
                #pragma unroll
                for (int c = 0; c < 4; c++)
                    po[ii][c] -= w0 * W[c][0] + w1 * W[c][1]
                               + w2 * W[c][2] + w3 * W[c][3];
                #pragma unroll
                for (int c = 0; c < 4; c++)
                    po[ii][4 + c] -= w0 * pW[c][0] + w1 * pW[c][1]
                                   + w2 * pW[c][2] + w3 * pW[c][3];
            }
            #pragma unroll
            for (int ii = 0; ii < 2; ii++) {
                const int i = 2 * half + ii;
                const int A = rb + 2 + 8 * h + 2 * i;
                Buf4[A + h]     = make_float4(po[ii][0], po[ii][1], po[ii][2], po[ii][3]);
                Buf4[A + 1 - h] = make_float4(po[ii][4], po[ii][5], po[ii][6], po[ii][7]);
            }
        }
    }

    __syncthreads();

    if (t == 0) {
        unsigned sa = (unsigned)__cvta_generic_to_shared(&Buf4[0]);
        float4* gdst = out4 + (size_t)b0 * 18;
        int bytes = nbb * 18 * 16;
        asm volatile("fence.proxy.async.shared::cta;" ::: "memory");
        asm volatile(
            "cp.async.bulk.global.shared::cta.bulk_group [%0], [%1], %2;"
            :: "l"(gdst), "r"(sa), "r"(bytes) : "memory");
        asm volatile("cp.async.bulk.commit_group;" ::: "memory");
        asm volatile("cp.async.bulk.wait_group.read 0;" ::: "memory");
    }
}

// ===========================================================================
// Host launcher
// ===========================================================================
typedef CUresult (*pfn_encode_t)(
    CUtensorMap*, CUtensorMapDataType, cuuint32_t, void*,
    const cuuint64_t*, const cuuint64_t*, const cuuint32_t*, const cuuint32_t*,
    CUtensorMapInterleave, CUtensorMapSwizzle, CUtensorMapL2promotion,
    CUtensorMapFloatOOBfill);

extern "C" void kernel_launch(void* const* d_in, const int* in_sizes, int n_in,
                              void* d_out, int out_size) {
    const float4* x4 = (const float4*)d_in[0];
    const float4* z4 = (const float4*)d_in[1];
    const float4* P4 = (const float4*)d_in[2];
    const float*  Hg = (const float*)d_in[3];
    const float*  Rg = (const float*)d_in[4];
    float4* out4 = (float4*)d_out;

    int nb = in_sizes[0] / 8;                    // B
    int grid = (nb + BPB - 1) / BPB;

    // Resolve cuTensorMapEncodeTiled through the runtime (no -lcuda needed).
    void* fp = nullptr;
    cudaDriverEntryPointQueryResult qr = cudaDriverEntryPointSymbolNotFound;
    bool ok = (cudaGetDriverEntryPoint("cuTensorMapEncodeTiled", &fp,
                                       cudaEnableDefault, &qr) == cudaSuccess)
              && fp != nullptr && qr == cudaDriverEntryPointSuccess;

    CUtensorMap mL, mP, mX;
    if (ok) {
        pfn_encode_t enc = (pfn_encode_t)fp;
        cuuint32_t es[3] = {1, 1, 1};

        // P load: [128B][2][B], record stride 256B, SW128
        {
            cuuint64_t dims[3] = {128, 2, (cuuint64_t)nb};
            cuuint64_t str[2]  = {128, 256};
            cuuint32_t box[3]  = {128, 2, BPB};
            ok = ok && enc(&mL, CU_TENSOR_MAP_DATA_TYPE_UINT8, 3, (void*)P4,
                           dims, str, box, es,
                           CU_TENSOR_MAP_INTERLEAVE_NONE,
                           CU_TENSOR_MAP_SWIZZLE_128B,
                           CU_TENSOR_MAP_L2_PROMOTION_L2_128B,
                           CU_TENSOR_MAP_FLOAT_OOB_FILL_NONE) == CUDA_SUCCESS;
        }
        // P store: [128B][2][B] into output P-part (record stride 288B, +32B), SW128
        {
            cuuint64_t dims[3] = {128, 2, (cuuint64_t)nb};
            cuuint64_t str[2]  = {128, 288};
            cuuint32_t box[3]  = {128, 2, BPB};
            ok = ok && enc(&mP, CU_TENSOR_MAP_DATA_TYPE_UINT8, 3,
                           (void*)((char*)d_out + 32),
                           dims, str, box, es,
                           CU_TENSOR_MAP_INTERLEAVE_NONE,
                           CU_TENSOR_MAP_SWIZZLE_128B,
                           CU_TENSOR_MAP_L2_PROMOTION_L2_128B,
                           CU_TENSOR_MAP_FLOAT_OOB_FILL_NONE) == CUDA_SUCCESS;
        }
        // x store: [32B][B] at record offset 0 (stride 288B), no swizzle
        {
            cuuint64_t dims[2] = {32, (cuuint64_t)nb};
            cuuint64_t str[1]  = {288};
            cuuint32_t box[2]  = {32, BPB};
            ok = ok && enc(&mX, CU_TENSOR_MAP_DATA_TYPE_UINT8, 2, d_out,
                           dims, str, box, es,
                           CU_TENSOR_MAP_INTERLEAVE_NONE,
                           CU_TENSOR_MAP_SWIZZLE_NONE,
                           CU_TENSOR_MAP_L2_PROMOTION_L2_128B,
                           CU_TENSOR_MAP_FLOAT_OOB_FILL_NONE) == CUDA_SUCCESS;
        }
    }

    if (ok) {
        kalman_tma<<<grid, NT>>>(x4, z4, Hg, Rg, nb, mL, mP, mX);
    } else {
        kalman_fb<<<grid, NT>>>(x4, z4, P4, Hg, Rg, out4, nb);
    }
}

// round 17
// speedup vs baseline: 1.5746x; 1.1735x over previous
#include <cuda_runtime.h>
#include <cuda_pipeline.h>
#include <cuda_bf16.h>

// Batched Kalman update: B=262144, DX=8, DZ=4.  TWO threads per batch.
// Pair = lanes (2m, 2m+1); thread h owns rows 4h..4h+3.
//
// == R12 (best, 29.4us) + ONE delta: P staging uses cp.async.cg (LDGSTS)
// instead of LDG->reg->STS: removes the STS wavefronts from the L1 pipe,
// frees staging registers, and decouples the load from the store issue.
// Same conflict-free destination mapping (m = hw+8k, consecutive quads per
// 8-lane phase), same coalesced 16B-per-thread global pattern.
//
// Parity-interleaved SREG=18: every row access touches its two quads in
// h-swapped order (Buf4[A+h], Buf4[A+1-h]) -> h0 lanes on even quads, h1 on
// odd quads in the same instruction -> conflict-free; qa always holds own
// cols 4h..4h+3 so ALL epilogue indices are static.  Region == output
// record; block results drained by one cp.async.bulk (TMA pipe).
//
// W-form math (== Joseph form for the optimal gain):
//   PHT = P H^T, S = H PHT + R = L L^T;  W = PHT L^-T,  u = L^-1 y
//   x_new = x + W u,  P_new = P - W W^T

#define NT   128
#define BPB  64
#define SREG 18

__global__ void __launch_bounds__(NT, 8) kalman_kernel(
    const float4* __restrict__ x4,
    const float4* __restrict__ z4,
    const float4* __restrict__ P4,
    const float*  __restrict__ Hg,
    const float*  __restrict__ Rg,
    float4*       __restrict__ out4,
    int nb)
{
    __shared__ float4 Buf4[BPB * SREG];   // 18432 B, contiguous output image
    __shared__ float4 HT4[8];             // HT4[k] = H[0..3][k]
    __shared__ float  Rs[16];

    const int t   = threadIdx.x;
    const int b0  = blockIdx.x * BPB;
    const int nbb = min(BPB, nb - b0);

    if (t < 8)  HT4[t] = make_float4(Hg[t], Hg[8 + t], Hg[16 + t], Hg[24 + t]);
    if (t >= 32 && t < 48) Rs[t - 32] = Rg[t - 32];

    // ---- Stage P via cp.async (LDGSTS): gmem 16B/thread coalesced ->
    //      conflict-free consecutive smem quads, no register round trip ----
    {
        const int hw = t >> 4;            // half-warp id 0..7
        const int fq = t & 15;            // quad-in-record
        #pragma unroll
        for (int k = 0; k < 8; k++) {
            int m = hw + 8 * k;
            if (m < nbb)
                __pipeline_memcpy_async(&Buf4[m * SREG + 2 + fq],
                                        &P4[(size_t)b0 * 16 + 16 * m + fq],
                                        16);
        }
        __pipeline_commit();
    }

    // ---- Direct loads: x quad (elems 4h..4h+3) on its owner; z per pair ----
    float4 xq = make_float4(0.f, 0.f, 0.f, 0.f);
    float4 zq = make_float4(0.f, 0.f, 0.f, 0.f);
    if (t < 2 * nbb) {
        xq = x4[(size_t)b0 * 2 + t];
        zq = z4[b0 + (t >> 1)];
    }

    __pipeline_wait_prior(0);
    __syncthreads();

    if (t < 2 * nbb) {
        const int m  = t >> 1;
        const int h  = t & 1;
        const int rb = m * SREG;
        const int hb1 = 4 * h;            // HT base for qa cols (own)
        const int hb2 = 4 - 4 * h;        // HT base for qb cols (partner)
        const unsigned FM = 0xffffffffu;

        // ---- y = z - H x (pair-partial; own elems are cols 4h..4h+3) ----
        float xo0 = xq.x, xo1 = xq.y, xo2 = xq.z, xo3 = xq.w;
        float s0, s1, s2, s3;
        {
            float4 ha = HT4[hb1 + 0], hb = HT4[hb1 + 1];
            float4 hc = HT4[hb1 + 2], hd = HT4[hb1 + 3];
            s0 = ha.x * xo0 + hb.x * xo1 + hc.x * xo2 + hd.x * xo3;
            s1 = ha.y * xo0 + hb.y * xo1 + hc.y * xo2 + hd.y * xo3;
            s2 = ha.z * xo0 + hb.z * xo1 + hc.z * xo2 + hd.z * xo3;
            s3 = ha.w * xo0 + hb.w * xo1 + hc.w * xo2 + hd.w * xo3;
        }
        float y0 = zq.x - (s0 + __shfl_xor_sync(FM, s0, 1));
        float y1 = zq.y - (s1 + __shfl_xor_sync(FM, s1, 1));
        float y2 = zq.z - (s2 + __shfl_xor_sync(FM, s2, 1));
        float y3 = zq.w - (s3 + __shfl_xor_sync(FM, s3, 1));

        // ---- W = PHT for own rows 4h+i (parity-swapped quad reads) ----
        float W[4][4];
        #pragma unroll
        for (int i = 0; i < 4; i++) {
            const int A = rb + 2 + 8 * h + 2 * i;   // quad pair base of row 4h+i
            float4 qa = Buf4[A + h];                // cols 4h..4h+3
            float4 qb = Buf4[A + 1 - h];            // cols 4(1-h)..
            float q0, q1, q2, q3;
            {
                float4 c0 = HT4[hb1 + 0], c1 = HT4[hb1 + 1];
                float4 c2 = HT4[hb1 + 2], c3 = HT4[hb1 + 3];
                q0 = qa.x * c0.x + qa.y * c1.x + qa.z * c2.x + qa.w * c3.x;
                q1 = qa.x * c0.y + qa.y * c1.y + qa.z * c2.y + qa.w * c3.y;
                q2 = qa.x * c0.z + qa.y * c1.z + qa.z * c2.z + qa.w * c3.z;
                q3 = qa.x * c0.w + qa.y * c1.w + qa.z * c2.w + qa.w * c3.w;
            }
            {
                float4 c0 = HT4[hb2 + 0], c1 = HT4[hb2 + 1];
                float4 c2 = HT4[hb2 + 2], c3 = HT4[hb2 + 3];
                q0 += qb.x * c0.x + qb.y * c1.x + qb.z * c2.x + qb.w * c3.x;
                q1 += qb.x * c0.y + qb.y * c1.y + qb.z * c2.y + qb.w * c3.y;
                q2 += qb.x * c0.z + qb.y * c1.z + qb.z * c2.z + qb.w * c3.z;
                q3 += qb.x * c0.w + qb.y * c1.w + qb.z * c2.w + qb.w * c3.w;
            }
            W[i][0] = q0; W[i][1] = q1; W[i][2] = q2; W[i][3] = q3;
        }

        // ---- S partial from own rows (row 4h+i -> HT4[4h+i]), pair-reduce ----
        float S00 = 0.f, S01 = 0.f, S02 = 0.f, S03 = 0.f;
        float S11 = 0.f, S12 = 0.f, S13 = 0.f;
        float S22 = 0.f, S23 = 0.f, S33 = 0.f;
        #pragma unroll
        for (int i = 0; i < 4; i++) {
            float4 ht = HT4[hb1 + i];
            float q0 = W[i][0], q1 = W[i][1], q2 = W[i][2], q3 = W[i][3];
            S00 += ht.x * q0; S01 += ht.x * q1; S02 += ht.x * q2; S03 += ht.x * q3;
            S11 += ht.y * q1; S12 += ht.y * q2; S13 += ht.y * q3;
            S22 += ht.z * q2; S23 += ht.z * q3;
            S33 += ht.w * q3;
        }
        S00 += __shfl_xor_sync(FM, S00, 1); S01 += __shfl_xor_sync(FM, S01, 1);
        S02 += __shfl_xor_sync(FM, S02, 1); S03 += __shfl_xor_sync(FM, S03, 1);
        S11 += __shfl_xor_sync(FM, S11, 1); S12 += __shfl_xor_sync(FM, S12, 1);
        S13 += __shfl_xor_sync(FM, S13, 1); S22 += __shfl_xor_sync(FM, S22, 1);
        S23 += __shfl_xor_sync(FM, S23, 1); S33 += __shfl_xor_sync(FM, S33, 1);
        S00 += Rs[0];  S01 += Rs[1];  S02 += Rs[2];  S03 += Rs[3];
        S11 += Rs[5];  S12 += Rs[6];  S13 += Rs[7];
        S22 += Rs[10]; S23 += Rs[11]; S33 += Rs[15];

        // ---- Cholesky ----
        float i0  = rsqrtf(S00);
        float l10 = S01 * i0, l20 = S02 * i0, l30 = S03 * i0;
        float i1  = rsqrtf(S11 - l10 * l10);
        float l21 = (S12 - l20 * l10) * i1;
        float l31 = (S13 - l30 * l10) * i1;
        float i2  = rsqrtf(S22 - l20 * l20 - l21 * l21);
        float l32 = (S23 - l30 * l20 - l31 * l21) * i2;
        float i3  = rsqrtf(S33 - l30 * l30 - l31 * l31 - l32 * l32);

        // ---- W <- W L^-T ----
        #pragma unroll
        for (int i = 0; i < 4; i++) {
            float w0 = W[i][0] * i0;
            float w1 = (W[i][1] - l10 * w0) * i1;
            float w2 = (W[i][2] - l20 * w0 - l21 * w1) * i2;
            float w3 = (W[i][3] - l30 * w0 - l31 * w1 - l32 * w2) * i3;
            W[i][0] = w0; W[i][1] = w1; W[i][2] = w2; W[i][3] = w3;
        }

        // ---- u = L^-1 y ----
        float u0 = y0 * i0;
        float u1 = (y1 - l10 * u0) * i1;
        float u2 = (y2 - l20 * u0 - l21 * u1) * i2;
        float u3 = (y3 - l30 * u0 - l31 * u1 - l32 * u2) * i3;

        // ---- x_new own quad: elem 4h+i pairs with own W[i] (static) ----
        Buf4[rb + h] = make_float4(
            xo0 + W[0][0]*u0 + W[0][1]*u1 + W[0][2]*u2 + W[0][3]*u3,
            xo1 + W[1][0]*u0 + W[1][1]*u1 + W[1][2]*u2 + W[1][3]*u3,
            xo2 + W[2][0]*u0 + W[2][1]*u1 + W[2][2]*u2 + W[2][3]*u3,
            xo3 + W[3][0]*u0 + W[3][1]*u1 + W[3][2]*u2 + W[3][3]*u3);

        // ---- Partner W via 16 xor-shuffles: pW[s] = partner row 4(1-h)+s ----
        float pW[4][4];
        #pragma unroll
        for (int s = 0; s < 4; s++)
            #pragma unroll
            for (int c = 0; c < 4; c++)
                pW[s][c] = __shfl_xor_sync(FM, W[s][c], 1);

        // ---- P_new = P - W W^T, two 2-row halves; ALL indices static ----
        // po[c]   = col 4h+c     -> subtract W[i].W[c]   (own rows)
        // po[4+c] = col 4(1-h)+c -> subtract W[i].pW[c]  (partner rows)
        #pragma unroll
        for (int half = 0; half < 2; half++) {
            float po[2][8];
            #pragma unroll
            for (int ii = 0; ii < 2; ii++) {
                const int i = 2 * half + ii;
                const int A = rb + 2 + 8 * h + 2 * i;
                float4 qa = Buf4[A + h];
                float4 qb = Buf4[A + 1 - h];
                po[ii][0] = qa.x; po[ii][1] = qa.y; po[ii][2] = qa.z; po[ii][3] = qa.w;
                po[ii][4] = qb.x; po[ii][5] = qb.y; po[ii][6] = qb.z; po[ii][7] = qb.w;
            }
            #pragma unroll
            for (int ii = 0; ii < 2; ii++) {
                const int i = 2 * half + ii;
                float w0 = W[i][0], w1 = W[i][1], w2 = W[i][2], w3 = W[i][3];
                #pragma unroll
                for (int c = 0; c < 4; c++)
                    po[ii][c] -= w0 * W[c][0] + w1 * W[c][1]
                               + w2 * W[c][2] + w3 * W[c][3];
                #pragma unroll
                for (int c = 0; c < 4; c++)
                    po[ii][4 + c] -= w0 * pW[c][0] + w1 * pW[c][1]
                                   + w2 * pW[c][2] + w3 * pW[c][3];
            }
            #pragma unroll
            for (int ii = 0; ii < 2; ii++) {
                const int i = 2 * half + ii;
                const int A = rb + 2 + 8 * h + 2 * i;
                Buf4[A + h]     = make_float4(po[ii][0], po[ii][1], po[ii][2], po[ii][3]);
                Buf4[A + 1 - h] = make_float4(po[ii][4], po[ii][5], po[ii][6], po[ii][7]);
            }
        }
    }

    __syncthreads();

    // ---- Drain: one contiguous bulk copy SMEM -> GMEM via the TMA pipe ----
    if (t == 0) {
        unsigned sa = (unsigned)__cvta_generic_to_shared(&Buf4[0]);
        float4* gdst = out4 + (size_t)b0 * 18;
        int bytes = nbb * 18 * 16;
        asm volatile("fence.proxy.async.shared::cta;" ::: "memory");
        asm volatile(
            "cp.async.bulk.global.shared::cta.bulk_group [%0], [%1], %2;"
            :: "l"(gdst), "r"(sa), "r"(bytes) : "memory");
        asm volatile("cp.async.bulk.commit_group;" ::: "memory");
        asm volatile("cp.async.bulk.wait_group.read 0;" ::: "memory");
    }
}

extern "C" void kernel_launch(void* const* d_in, const int* in_sizes, int n_in,
                              void* d_out, int out_size) {
    const float4* x4 = (const float4*)d_in[0];
    const float4* z4 = (const float4*)d_in[1];
    const float4* P4 = (const float4*)d_in[2];
    const float*  Hg = (const float*)d_in[3];
    const float*  Rg = (const float*)d_in[4];
    float4* out4 = (float4*)d_out;

    int nb = in_sizes[0] / 8;            // B
    int grid = (nb + BPB - 1) / BPB;
    kalman_kernel<<<grid, NT>>>(x4, z4, P4, Hg, Rg, out4, nb);
}